// round 13
// baseline (speedup 1.0000x reference)
#include <cuda_runtime.h>

#define CC 192
#define HW4 2304u     // H*W/4 = groups per channel
#define PSTRIDE 59    // 33 softplus(mat) + 13 bias + 13 tanh(factor)

__device__ __forceinline__ float fast_sigmoid(float x) {
    float e = __expf(-x);
    return __fdividef(1.0f, 1.0f + e);
}

__device__ __forceinline__ float fast_tanh(float x) {
    float y;
    asm("tanh.approx.f32 %0, %1;" : "=f"(y) : "f"(x));
    return y;
}

__device__ __forceinline__ float softplus_fast(float x) {
    return (x > 15.0f) ? x : __logf(1.0f + __expf(x));
}

// -------------------------------------------------------------------------
// Generic slow logits (gated fallback only). Reads transformed params from
// the warp's shared slab; loop-kept so it never taxes fast-path registers.
// -------------------------------------------------------------------------
__device__ __noinline__ float logits_slow(const float* P, float t)
{
    float h[3];
#pragma unroll 1
    for (int i = 0; i < 3; i++) {
        float g = fmaf(P[i], t, P[33 + i]);
        h[i] = g + P[46 + i] * tanhf(g);
    }
#pragma unroll 1
    for (int l = 1; l < 4; l++) {
        const float* M = P + 3 + (l - 1) * 9;
        float g[3];
#pragma unroll 1
        for (int r = 0; r < 3; r++) {
            float s = P[33 + 3 * l + r];
#pragma unroll 1
            for (int k = 0; k < 3; k++) s = fmaf(M[3 * r + k], h[k], s);
            g[r] = s + P[46 + 3 * l + r] * tanhf(s);
        }
        h[0] = g[0]; h[1] = g[1]; h[2] = g[2];
    }
    float o = P[33 + 12];
#pragma unroll 1
    for (int k = 0; k < 3; k++) o = fmaf(P[30 + k], h[k], o);
    return o + P[46 + 12] * tanhf(o);
}

__device__ __forceinline__ float lk_from_LU(float L, float U)
{
    float su = L + U;
    float s = (su > 0.0f) ? -1.0f : ((su < 0.0f) ? 1.0f : 0.0f);  // -sign(L+U)
    float lk = fabsf(fast_sigmoid(s * U) - fast_sigmoid(s * L));
    return fmaxf(lk, 1e-9f);
}

// -------------------------------------------------------------------------
// Single fused kernel, v3: WARP-AUTONOMOUS prologue, zero block barriers.
// Each warp owns 64 consecutive float4-groups (64 | 2304 -> warp is always
// channel-uniform). Per warp: issue the 4 streaming loads, transform the
// channel's 59 params into a private shared slab (__syncwarp only), then
// ALL lanes redundantly compose the affine collapse logits(t)=a*t+b from
// shared (warp-uniform -> same issue cost as one lane, no broadcast). The
// prologue's dependency chain hides under the warp's own input-load
// latency. Exact when all tanh gates are zero; gated fallback reads the
// shared slab.
// -------------------------------------------------------------------------
__global__ void __launch_bounds__(256) eb_fused(
    const float4* __restrict__ x4, const float4* __restrict__ n4,
    float* __restrict__ out, int n4tot,
    const float* __restrict__ m0, const float* __restrict__ m1,
    const float* __restrict__ m2, const float* __restrict__ m3,
    const float* __restrict__ m4,
    const float* __restrict__ b0, const float* __restrict__ b1,
    const float* __restrict__ b2, const float* __restrict__ b3,
    const float* __restrict__ b4,
    const float* __restrict__ f0, const float* __restrict__ f1,
    const float* __restrict__ f2, const float* __restrict__ f3,
    const float* __restrict__ f4)
{
    __shared__ float S[8][PSTRIDE];
    int warp = threadIdx.x >> 5;
    int lane = threadIdx.x & 31;

    unsigned wb = blockIdx.x * 512u + (unsigned)warp * 64u;  // warp's first group
    unsigned g0 = wb + (unsigned)lane;
    unsigned g1 = g0 + 32u;

    // Streaming loads first — the prologue hides under their latency.
    float4 xv0 = __ldcs(x4 + g0);
    float4 nv0 = __ldcs(n4 + g0);
    float4 xv1 = __ldcs(x4 + g1);
    float4 nv1 = __ldcs(n4 + g1);

    unsigned c = (wb / HW4) % CC;   // channel, uniform across the warp

    float* W = S[warp];
#pragma unroll
    for (int pass = 0; pass < 2; pass++) {
        int s = lane + pass * 32;
        if (s < PSTRIDE) {
            float val;
            if (s < 33) {
                const float* ms[5] = {m0, m1, m2, m3, m4};
                const int moff[5] = {0, 3, 12, 21, 30};
                const int msz[5]  = {3, 9, 9, 9, 3};
                int l = (s < 3) ? 0 : (s < 12) ? 1 : (s < 21) ? 2 : (s < 30) ? 3 : 4;
                val = softplus_fast(ms[l][c * msz[l] + (s - moff[l])]);
            } else if (s < 46) {
                const float* bs[5] = {b0, b1, b2, b3, b4};
                const int uoff[5] = {0, 3, 6, 9, 12};
                const int usz[5]  = {3, 3, 3, 3, 1};
                int u = s - 33;
                int l = (u < 3) ? 0 : (u < 6) ? 1 : (u < 9) ? 2 : (u < 12) ? 3 : 4;
                val = bs[l][c * usz[l] + (u - uoff[l])];
            } else {
                const float* fs[5] = {f0, f1, f2, f3, f4};
                const int uoff[5] = {0, 3, 6, 9, 12};
                const int usz[5]  = {3, 3, 3, 3, 1};
                int u = s - 46;
                int l = (u < 3) ? 0 : (u < 6) ? 1 : (u < 9) ? 2 : (u < 12) ? 3 : 4;
                val = fast_tanh(fs[l][c * usz[l] + (u - uoff[l])]);
            }
            W[s] = val;
        }
    }
    __syncwarp();

    // Outputs v = x + noise are independent of params: compute & store now,
    // while the shared-composition below fills the remaining latency.
    float4 v0 = make_float4(xv0.x + nv0.x, xv0.y + nv0.y, xv0.z + nv0.z, xv0.w + nv0.w);
    float4 v1 = make_float4(xv1.x + nv1.x, xv1.y + nv1.y, xv1.z + nv1.z, xv1.w + nv1.w);
    float4* o4 = (float4*)out;
    __stcs(o4 + g0, v0);
    __stcs(o4 + g1, v1);

    // Redundant (warp-uniform) affine composition from shared.
    const float* sp = W;
    const float* bb = W + 33;
    const float* tf = W + 46;

    bool gated = false;
#pragma unroll
    for (int i = 0; i < 13; i++) gated = gated || (tf[i] != 0.0f);

    float a0 = sp[0], a1 = sp[1], a2 = sp[2];
    float w0 = bb[0], w1 = bb[1], w2 = bb[2];
#pragma unroll
    for (int l = 1; l < 4; l++) {
        const float* M = sp + 3 + (l - 1) * 9;
        const float* B = bb + 3 * l;
        float na0 = M[0]*a0 + M[1]*a1 + M[2]*a2;
        float na1 = M[3]*a0 + M[4]*a1 + M[5]*a2;
        float na2 = M[6]*a0 + M[7]*a1 + M[8]*a2;
        float nw0 = M[0]*w0 + M[1]*w1 + M[2]*w2 + B[0];
        float nw1 = M[3]*w0 + M[4]*w1 + M[5]*w2 + B[1];
        float nw2 = M[6]*w0 + M[7]*w1 + M[8]*w2 + B[2];
        a0 = na0; a1 = na1; a2 = na2;
        w0 = nw0; w1 = nw1; w2 = nw2;
    }
    float a  = sp[30]*a0 + sp[31]*a1 + sp[32]*a2;
    float bS = sp[30]*w0 + sp[31]*w1 + sp[32]*w2 + bb[12];
    float bm = bS - 0.5f * a;

    float4 lk0, lk1;
    if (!gated) {
        float L0x = fmaf(a, v0.x, bm), L0y = fmaf(a, v0.y, bm);
        float L0z = fmaf(a, v0.z, bm), L0w = fmaf(a, v0.w, bm);
        lk0.x = lk_from_LU(L0x, L0x + a);
        lk0.y = lk_from_LU(L0y, L0y + a);
        lk0.z = lk_from_LU(L0z, L0z + a);
        lk0.w = lk_from_LU(L0w, L0w + a);
        float L1x = fmaf(a, v1.x, bm), L1y = fmaf(a, v1.y, bm);
        float L1z = fmaf(a, v1.z, bm), L1w = fmaf(a, v1.w, bm);
        lk1.x = lk_from_LU(L1x, L1x + a);
        lk1.y = lk_from_LU(L1y, L1y + a);
        lk1.z = lk_from_LU(L1z, L1z + a);
        lk1.w = lk_from_LU(L1w, L1w + a);
    } else {
        lk0.x = lk_from_LU(logits_slow(W, v0.x - 0.5f), logits_slow(W, v0.x + 0.5f));
        lk0.y = lk_from_LU(logits_slow(W, v0.y - 0.5f), logits_slow(W, v0.y + 0.5f));
        lk0.z = lk_from_LU(logits_slow(W, v0.z - 0.5f), logits_slow(W, v0.z + 0.5f));
        lk0.w = lk_from_LU(logits_slow(W, v0.w - 0.5f), logits_slow(W, v0.w + 0.5f));
        lk1.x = lk_from_LU(logits_slow(W, v1.x - 0.5f), logits_slow(W, v1.x + 0.5f));
        lk1.y = lk_from_LU(logits_slow(W, v1.y - 0.5f), logits_slow(W, v1.y + 0.5f));
        lk1.z = lk_from_LU(logits_slow(W, v1.z - 0.5f), logits_slow(W, v1.z + 0.5f));
        lk1.w = lk_from_LU(logits_slow(W, v1.w - 0.5f), logits_slow(W, v1.w + 0.5f));
    }
    __stcs(o4 + n4tot + g0, lk0);
    __stcs(o4 + n4tot + g1, lk1);
}

extern "C" void kernel_launch(void* const* d_in, const int* in_sizes, int n_in,
                              void* d_out, int out_size)
{
    const float* X  = (const float*)d_in[0];
    const float* NZ = (const float*)d_in[1];

    const float *m[5], *b[5], *f[5];
    if (in_sizes[3] == 3 * in_sizes[2]) {      // signature order
        for (int i = 0; i < 5; i++) {
            m[i] = (const float*)d_in[2 + i];
            b[i] = (const float*)d_in[7 + i];
            f[i] = (const float*)d_in[12 + i];
        }
    } else {                                   // dict order m,b,f interleaved
        for (int i = 0; i < 5; i++) {
            m[i] = (const float*)d_in[2 + 3 * i];
            b[i] = (const float*)d_in[3 + 3 * i];
            f[i] = (const float*)d_in[4 + 3 * i];
        }
    }

    int N = in_sizes[0];  // B*C*H*W = 28,311,552
    int blocks = N / 2048;  // 256 threads * 8 elems

    eb_fused<<<blocks, 256>>>(
        (const float4*)X, (const float4*)NZ, (float*)d_out, N / 4,
        m[0], m[1], m[2], m[3], m[4],
        b[0], b[1], b[2], b[3], b[4],
        f[0], f[1], f[2], f[3], f[4]);
}

// round 14
// speedup vs baseline: 1.3140x; 1.3140x over previous
#include <cuda_runtime.h>

#define CC 192
#define HW4 2304u     // H*W/4 = float4-groups per channel
#define PSTRIDE 59    // 33 softplus(mat) + 13 bias + 13 tanh(factor)
#define NFLAG 64

__device__ float    d_param[CC * PSTRIDE];
__device__ float4   d_affine[CC];          // {a, b-0.5a, gated, b}
__device__ unsigned d_flagv[NFLAG * 32];   // one flag per 128B line, zero-init
__device__ unsigned d_done = 0;

__device__ __forceinline__ float fast_sigmoid(float x) {
    float e = __expf(-x);
    return __fdividef(1.0f, 1.0f + e);
}

__device__ __forceinline__ float fast_tanh(float x) {
    float y;
    asm("tanh.approx.f32 %0, %1;" : "=f"(y) : "f"(x));
    return y;
}

__device__ __forceinline__ float softplus_fast(float x) {
    return (x > 15.0f) ? x : __logf(1.0f + __expf(x));
}

// -------------------------------------------------------------------------
// Per-channel prep, registers only. Runs on block 0 threads 0..191 (one
// channel each). Writes the transformed parameter block (gated fallback)
// and the affine collapse logits(t)=a*t+b (exact when tanh gates are 0).
// __noinline__: any spills stay out of the streaming fast path.
// -------------------------------------------------------------------------
__device__ __noinline__ void prep_channel(int c,
    const float* m0, const float* m1, const float* m2,
    const float* m3, const float* m4,
    const float* b0, const float* b1, const float* b2,
    const float* b3, const float* b4,
    const float* f0, const float* f1, const float* f2,
    const float* f3, const float* f4)
{
    float* P = d_param + c * PSTRIDE;

    float a0 = softplus_fast(m0[c*3+0]); P[0] = a0;
    float a1 = softplus_fast(m0[c*3+1]); P[1] = a1;
    float a2 = softplus_fast(m0[c*3+2]); P[2] = a2;
    float v0 = b0[c*3+0]; P[33] = v0;
    float v1 = b0[c*3+1]; P[34] = v1;
    float v2 = b0[c*3+2]; P[35] = v2;

    const float* mm[3] = {m1 + c*9, m2 + c*9, m3 + c*9};
    const float* bp[3] = {b1 + c*3, b2 + c*3, b3 + c*3};
#pragma unroll 1
    for (int l = 0; l < 3; l++) {
        const float* M = mm[l];
        const float* B = bp[l];
        float s[9];
#pragma unroll
        for (int j = 0; j < 9; j++) { s[j] = softplus_fast(M[j]); P[3 + l*9 + j] = s[j]; }
        float bv0 = B[0], bv1 = B[1], bv2 = B[2];
        P[36 + l*3 + 0] = bv0; P[36 + l*3 + 1] = bv1; P[36 + l*3 + 2] = bv2;
        float na0 = s[0]*a0 + s[1]*a1 + s[2]*a2;
        float na1 = s[3]*a0 + s[4]*a1 + s[5]*a2;
        float na2 = s[6]*a0 + s[7]*a1 + s[8]*a2;
        float nv0 = s[0]*v0 + s[1]*v1 + s[2]*v2 + bv0;
        float nv1 = s[3]*v0 + s[4]*v1 + s[5]*v2 + bv1;
        float nv2 = s[6]*v0 + s[7]*v1 + s[8]*v2 + bv2;
        a0 = na0; a1 = na1; a2 = na2;
        v0 = nv0; v1 = nv1; v2 = nv2;
    }

    float s0 = softplus_fast(m4[c*3+0]); P[30] = s0;
    float s1 = softplus_fast(m4[c*3+1]); P[31] = s1;
    float s2 = softplus_fast(m4[c*3+2]); P[32] = s2;
    float bb12 = b4[c]; P[45] = bb12;
    float a  = s0*a0 + s1*a1 + s2*a2;
    float bS = s0*v0 + s1*v1 + s2*v2 + bb12;

    bool gated = false;
    const float* ff[4] = {f0 + c*3, f1 + c*3, f2 + c*3, f3 + c*3};
#pragma unroll 1
    for (int l = 0; l < 4; l++) {
#pragma unroll
        for (int i = 0; i < 3; i++) {
            float tv = fast_tanh(ff[l][i]);
            P[46 + l*3 + i] = tv;
            gated = gated || (tv != 0.0f);
        }
    }
    { float tv = fast_tanh(f4[c]); P[58] = tv; gated = gated || (tv != 0.0f); }

    d_affine[c] = make_float4(a, bS - 0.5f * a, gated ? 1.0f : 0.0f, bS);
}

// -------------------------------------------------------------------------
// Generic slow logits (gated fallback only).
// -------------------------------------------------------------------------
__device__ __noinline__ float logits_slow(const float* __restrict__ P, float t)
{
    float h[3];
#pragma unroll 1
    for (int i = 0; i < 3; i++) {
        float g = fmaf(P[i], t, P[33 + i]);
        h[i] = g + P[46 + i] * tanhf(g);
    }
#pragma unroll 1
    for (int l = 1; l < 4; l++) {
        const float* M = P + 3 + (l - 1) * 9;
        float g[3];
#pragma unroll 1
        for (int r = 0; r < 3; r++) {
            float s = P[33 + 3 * l + r];
#pragma unroll 1
            for (int k = 0; k < 3; k++) s = fmaf(M[3 * r + k], h[k], s);
            g[r] = s + P[46 + 3 * l + r] * tanhf(s);
        }
        h[0] = g[0]; h[1] = g[1]; h[2] = g[2];
    }
    float o = P[33 + 12];
#pragma unroll 1
    for (int k = 0; k < 3; k++) o = fmaf(P[30 + k], h[k], o);
    return o + P[46 + 12] * tanhf(o);
}

__device__ __forceinline__ float lk_from_LU(float L, float U)
{
    float su = L + U;
    float s = (su > 0.0f) ? -1.0f : ((su < 0.0f) ? 1.0f : 0.0f);  // -sign(L+U)
    float lk = fabsf(fast_sigmoid(s * U) - fast_sigmoid(s * L));
    return fmaxf(lk, 1e-9f);
}

__device__ __forceinline__ float4 lk_group(float4 A, float4 v, unsigned c)
{
    float4 lk;
    if (A.z == 0.0f) {
        float a = A.x, bm = A.y;
        float Lx = fmaf(a, v.x, bm), Ly = fmaf(a, v.y, bm);
        float Lz = fmaf(a, v.z, bm), Lw = fmaf(a, v.w, bm);
        lk.x = lk_from_LU(Lx, Lx + a);
        lk.y = lk_from_LU(Ly, Ly + a);
        lk.z = lk_from_LU(Lz, Lz + a);
        lk.w = lk_from_LU(Lw, Lw + a);
    } else {
        const float* P = d_param + c * PSTRIDE;
        lk.x = lk_from_LU(logits_slow(P, v.x - 0.5f), logits_slow(P, v.x + 0.5f));
        lk.y = lk_from_LU(logits_slow(P, v.y - 0.5f), logits_slow(P, v.y + 0.5f));
        lk.z = lk_from_LU(logits_slow(P, v.z - 0.5f), logits_slow(P, v.z + 0.5f));
        lk.w = lk_from_LU(logits_slow(P, v.w - 0.5f), logits_slow(P, v.w + 0.5f));
    }
    return lk;
}

// -------------------------------------------------------------------------
// Single kernel, software-PDL. Block 0 preps all channels (registers only);
// publishes 64 distributed flags (release). Everyone streams: load inputs,
// store v (param-independent) BEFORE polling, then acquire-poll the flag,
// read d_affine, compute likelihood. Self-resetting handshake keeps graph
// replays deterministic. R10 streaming shape: 2 float4-groups/thread.
// -------------------------------------------------------------------------
__global__ void __launch_bounds__(256, 6) eb_all(
    const float4* __restrict__ x4, const float4* __restrict__ n4,
    float* __restrict__ out, int n4tot,
    const float* __restrict__ m0, const float* __restrict__ m1,
    const float* __restrict__ m2, const float* __restrict__ m3,
    const float* __restrict__ m4,
    const float* __restrict__ b0, const float* __restrict__ b1,
    const float* __restrict__ b2, const float* __restrict__ b3,
    const float* __restrict__ b4,
    const float* __restrict__ f0, const float* __restrict__ f1,
    const float* __restrict__ f2, const float* __restrict__ f3,
    const float* __restrict__ f4)
{
    unsigned g0 = blockIdx.x * 512u + threadIdx.x;
    unsigned g1 = g0 + 256u;

    // Streaming loads first.
    float4 xv0 = __ldcs(x4 + g0);
    float4 nv0 = __ldcs(n4 + g0);
    float4 xv1 = __ldcs(x4 + g1);
    float4 nv1 = __ldcs(n4 + g1);

    if (blockIdx.x == 0) {
        int t = threadIdx.x;
        if (t < CC)
            prep_channel(t, m0, m1, m2, m3, m4,
                         b0, b1, b2, b3, b4, f0, f1, f2, f3, f4);
        __syncthreads();
        if (t < NFLAG) {
            __threadfence();
            asm volatile("st.release.gpu.u32 [%0], %1;"
                         :: "l"(&d_flagv[t * 32]), "r"(1u) : "memory");
        }
    }

    // v = x + noise: independent of params — compute and store before poll.
    float4 v0 = make_float4(xv0.x + nv0.x, xv0.y + nv0.y, xv0.z + nv0.z, xv0.w + nv0.w);
    float4 v1 = make_float4(xv1.x + nv1.x, xv1.y + nv1.y, xv1.z + nv1.z, xv1.w + nv1.w);
    float4* o4 = (float4*)out;
    __stcs(o4 + g0, v0);
    __stcs(o4 + g1, v1);

    // Acquire-poll a distributed flag (avoids single-line L2 hotspot).
    {
        const unsigned* fp = &d_flagv[(blockIdx.x & (NFLAG - 1)) * 32];
        unsigned f;
        do {
            asm volatile("ld.acquire.gpu.u32 %0, [%1];"
                         : "=r"(f) : "l"(fp) : "memory");
        } while (f == 0);
    }

    unsigned c0 = (g0 / HW4) % CC;
    unsigned c1 = (g1 / HW4) % CC;
    float4 A0 = d_affine[c0];
    float4 A1 = d_affine[c1];

    float4 lk0 = lk_group(A0, v0, c0);
    float4 lk1 = lk_group(A1, v1, c1);
    __stcs(o4 + n4tot + g0, lk0);
    __stcs(o4 + n4tot + g1, lk1);

    // Reset handshake: last block to finish zeroes flags for the next call.
    __syncthreads();
    if (threadIdx.x == 0) {
        unsigned prev = atomicAdd(&d_done, 1u);
        if (prev == gridDim.x - 1) {
            d_done = 0;
#pragma unroll 1
            for (int i = 0; i < NFLAG; i++) d_flagv[i * 32] = 0;
        }
    }
}

extern "C" void kernel_launch(void* const* d_in, const int* in_sizes, int n_in,
                              void* d_out, int out_size)
{
    const float* X  = (const float*)d_in[0];
    const float* NZ = (const float*)d_in[1];

    const float *m[5], *b[5], *f[5];
    if (in_sizes[3] == 3 * in_sizes[2]) {      // signature order
        for (int i = 0; i < 5; i++) {
            m[i] = (const float*)d_in[2 + i];
            b[i] = (const float*)d_in[7 + i];
            f[i] = (const float*)d_in[12 + i];
        }
    } else {                                   // dict order m,b,f interleaved
        for (int i = 0; i < 5; i++) {
            m[i] = (const float*)d_in[2 + 3 * i];
            b[i] = (const float*)d_in[3 + 3 * i];
            f[i] = (const float*)d_in[4 + 3 * i];
        }
    }

    int N = in_sizes[0];  // B*C*H*W = 28,311,552
    int blocks = N / 2048;  // 256 threads * 8 elems

    eb_all<<<blocks, 256>>>(
        (const float4*)X, (const float4*)NZ, (float*)d_out, N / 4,
        m[0], m[1], m[2], m[3], m[4],
        b[0], b[1], b[2], b[3], b[4],
        f[0], f[1], f[2], f[3], f[4]);
}

// round 15
// speedup vs baseline: 1.5584x; 1.1860x over previous
#include <cuda_runtime.h>

#define CC 192
#define HW8 1152u     // H*W/8 = float8-groups per channel
#define PSTRIDE 59    // 33 softplus(mat) + 13 bias + 13 tanh(factor)

__device__ float  d_param[CC * PSTRIDE];
__device__ float4 d_affine[CC];   // {a, b - 0.5a, gated_flag, b}

struct __align__(32) F8 { float v[8]; };

__device__ __forceinline__ F8 ldcs8(const float* p) {
    F8 r;
    asm volatile("ld.global.cs.v8.f32 {%0,%1,%2,%3,%4,%5,%6,%7}, [%8];"
        : "=f"(r.v[0]), "=f"(r.v[1]), "=f"(r.v[2]), "=f"(r.v[3]),
          "=f"(r.v[4]), "=f"(r.v[5]), "=f"(r.v[6]), "=f"(r.v[7])
        : "l"(p));
    return r;
}

__device__ __forceinline__ void stcs8(float* p, const F8& r) {
    asm volatile("st.global.cs.v8.f32 [%0], {%1,%2,%3,%4,%5,%6,%7,%8};"
        :: "l"(p),
           "f"(r.v[0]), "f"(r.v[1]), "f"(r.v[2]), "f"(r.v[3]),
           "f"(r.v[4]), "f"(r.v[5]), "f"(r.v[6]), "f"(r.v[7])
        : "memory");
}

__device__ __forceinline__ float fast_sigmoid(float x) {
    float e = __expf(-x);
    return __fdividef(1.0f, 1.0f + e);
}

__device__ __forceinline__ float fast_tanh(float x) {
    float y;
    asm("tanh.approx.f32 %0, %1;" : "=f"(y) : "f"(x));
    return y;
}

__device__ __forceinline__ float softplus_fast(float x) {
    return (x > 15.0f) ? x : __logf(1.0f + __expf(x));
}

// -------------------------------------------------------------------------
// Prep: one WARP per channel (24 blocks x 8 warps). Fast intrinsics; lane 0
// composes the affine collapse logits(t)=a*t+b (exact when all tanh gates
// are zero). Signals PDL dependents after its global writes.
// -------------------------------------------------------------------------
__global__ void __launch_bounds__(256) eb_prep(
    const float* __restrict__ m0, const float* __restrict__ m1,
    const float* __restrict__ m2, const float* __restrict__ m3,
    const float* __restrict__ m4,
    const float* __restrict__ b0, const float* __restrict__ b1,
    const float* __restrict__ b2, const float* __restrict__ b3,
    const float* __restrict__ b4,
    const float* __restrict__ f0, const float* __restrict__ f1,
    const float* __restrict__ f2, const float* __restrict__ f3,
    const float* __restrict__ f4)
{
    __shared__ float S[8][PSTRIDE];
    int warp = threadIdx.x >> 5;
    int lane = threadIdx.x & 31;
    int c = blockIdx.x * 8 + warp;

    const float* ms[5] = {m0, m1, m2, m3, m4};
    const float* bs[5] = {b0, b1, b2, b3, b4};
    const float* fs[5] = {f0, f1, f2, f3, f4};
    const int moff[5] = {0, 3, 12, 21, 30};
    const int msz[5]  = {3, 9, 9, 9, 3};
    const int uoff[5] = {0, 3, 6, 9, 12};
    const int usz[5]  = {3, 3, 3, 3, 1};

#pragma unroll
    for (int pass = 0; pass < 2; pass++) {
        int s = lane + pass * 32;
        if (s < PSTRIDE) {
            float val;
            if (s < 33) {
                int l = (s < 3) ? 0 : (s < 12) ? 1 : (s < 21) ? 2 : (s < 30) ? 3 : 4;
                val = softplus_fast(ms[l][c * msz[l] + (s - moff[l])]);
            } else if (s < 46) {
                int u = s - 33;
                int l = (u < 3) ? 0 : (u < 6) ? 1 : (u < 9) ? 2 : (u < 12) ? 3 : 4;
                val = bs[l][c * usz[l] + (u - uoff[l])];
            } else {
                int u = s - 46;
                int l = (u < 3) ? 0 : (u < 6) ? 1 : (u < 9) ? 2 : (u < 12) ? 3 : 4;
                val = fast_tanh(fs[l][c * usz[l] + (u - uoff[l])]);
            }
            d_param[c * PSTRIDE + s] = val;
            S[warp][s] = val;
        }
    }
    __syncwarp();

    if (lane == 0) {
        const float* sp = S[warp];
        const float* bb = S[warp] + 33;
        const float* tf = S[warp] + 46;

        bool gated = false;
#pragma unroll
        for (int i = 0; i < 13; i++) gated = gated || (tf[i] != 0.0f);

        float a0 = sp[0], a1 = sp[1], a2 = sp[2];
        float v0 = bb[0], v1 = bb[1], v2 = bb[2];
#pragma unroll
        for (int l = 1; l < 4; l++) {
            const float* M = sp + 3 + (l - 1) * 9;
            const float* B = bb + 3 * l;
            float na0 = M[0]*a0 + M[1]*a1 + M[2]*a2;
            float na1 = M[3]*a0 + M[4]*a1 + M[5]*a2;
            float na2 = M[6]*a0 + M[7]*a1 + M[8]*a2;
            float nv0 = M[0]*v0 + M[1]*v1 + M[2]*v2 + B[0];
            float nv1 = M[3]*v0 + M[4]*v1 + M[5]*v2 + B[1];
            float nv2 = M[6]*v0 + M[7]*v1 + M[8]*v2 + B[2];
            a0 = na0; a1 = na1; a2 = na2;
            v0 = nv0; v1 = nv1; v2 = nv2;
        }
        float a_s = sp[30]*a0 + sp[31]*a1 + sp[32]*a2;
        float b_s = sp[30]*v0 + sp[31]*v1 + sp[32]*v2 + bb[12];

        d_affine[c] = make_float4(a_s, b_s - 0.5f * a_s, gated ? 1.0f : 0.0f, b_s);
    }
    asm volatile("griddepcontrol.launch_dependents;" ::: "memory");
}

// -------------------------------------------------------------------------
// Generic slow logits (gated fallback only).
// -------------------------------------------------------------------------
__device__ __noinline__ float logits_slow(const float* __restrict__ P, float t)
{
    float h[3];
#pragma unroll 1
    for (int i = 0; i < 3; i++) {
        float g = fmaf(P[i], t, P[33 + i]);
        h[i] = g + P[46 + i] * tanhf(g);
    }
#pragma unroll 1
    for (int l = 1; l < 4; l++) {
        const float* M = P + 3 + (l - 1) * 9;
        float g[3];
#pragma unroll 1
        for (int r = 0; r < 3; r++) {
            float s = P[33 + 3 * l + r];
#pragma unroll 1
            for (int k = 0; k < 3; k++) s = fmaf(M[3 * r + k], h[k], s);
            g[r] = s + P[46 + 3 * l + r] * tanhf(s);
        }
        h[0] = g[0]; h[1] = g[1]; h[2] = g[2];
    }
    float o = P[33 + 12];
#pragma unroll 1
    for (int k = 0; k < 3; k++) o = fmaf(P[30 + k], h[k], o);
    return o + P[46 + 12] * tanhf(o);
}

__device__ __forceinline__ float lk_from_LU(float L, float U)
{
    float su = L + U;
    float s = (su > 0.0f) ? -1.0f : ((su < 0.0f) ? 1.0f : 0.0f);  // -sign(L+U)
    float lk = fabsf(fast_sigmoid(s * U) - fast_sigmoid(s * L));
    return fmaxf(lk, 1e-9f);
}

// -------------------------------------------------------------------------
// Hot kernel: 256-bit global accesses. Each thread owns 8 consecutive
// floats (9216 % 8 == 0 -> channel-uniform): 2 v8 loads, 2 v8 stores.
// Half the LSU instructions / L1 wavefronts of the float4 version. PDL
// wait sits after the independent input loads.
// -------------------------------------------------------------------------
__global__ void __launch_bounds__(256, 6) eb_main(
    const float* __restrict__ xf, const float* __restrict__ nf,
    float* __restrict__ out, int N)
{
    unsigned g = blockIdx.x * 256u + threadIdx.x;   // float8-group index
    const float* xp = xf + (size_t)g * 8u;
    const float* np = nf + (size_t)g * 8u;

    F8 xv = ldcs8(xp);
    F8 nv = ldcs8(np);

    asm volatile("griddepcontrol.wait;" ::: "memory");

    unsigned c = (g / HW8) % CC;
    float4 A = d_affine[c];

    F8 v;
#pragma unroll
    for (int i = 0; i < 8; i++) v.v[i] = xv.v[i] + nv.v[i];

    stcs8(out + (size_t)g * 8u, v);   // outputs = v

    F8 lk;
    if (A.z == 0.0f) {
        float a = A.x, bm = A.y;
#pragma unroll
        for (int i = 0; i < 8; i++) {
            float L = fmaf(a, v.v[i], bm);
            lk.v[i] = lk_from_LU(L, L + a);
        }
    } else {
        const float* P = d_param + c * PSTRIDE;
#pragma unroll 1
        for (int i = 0; i < 8; i++)
            lk.v[i] = lk_from_LU(logits_slow(P, v.v[i] - 0.5f),
                                 logits_slow(P, v.v[i] + 0.5f));
    }
    stcs8(out + (size_t)N + (size_t)g * 8u, lk);  // likelihood
}

extern "C" void kernel_launch(void* const* d_in, const int* in_sizes, int n_in,
                              void* d_out, int out_size)
{
    const float* X  = (const float*)d_in[0];
    const float* NZ = (const float*)d_in[1];

    const float *m[5], *b[5], *f[5];
    if (in_sizes[3] == 3 * in_sizes[2]) {      // signature order
        for (int i = 0; i < 5; i++) {
            m[i] = (const float*)d_in[2 + i];
            b[i] = (const float*)d_in[7 + i];
            f[i] = (const float*)d_in[12 + i];
        }
    } else {                                   // dict order m,b,f interleaved
        for (int i = 0; i < 5; i++) {
            m[i] = (const float*)d_in[2 + 3 * i];
            b[i] = (const float*)d_in[3 + 3 * i];
            f[i] = (const float*)d_in[4 + 3 * i];
        }
    }

    int N = in_sizes[0];  // B*C*H*W = 28,311,552
    int blocks = N / 2048;  // 256 threads * 8 elems

    eb_prep<<<24, 256>>>(
        m[0], m[1], m[2], m[3], m[4],
        b[0], b[1], b[2], b[3], b[4],
        f[0], f[1], f[2], f[3], f[4]);

    cudaLaunchAttribute attr[1];
    attr[0].id = cudaLaunchAttributeProgrammaticStreamSerialization;
    attr[0].val.programmaticStreamSerializationAllowed = 1;

    cudaLaunchConfig_t cfg = {};
    cfg.gridDim  = dim3((unsigned)blocks, 1, 1);
    cfg.blockDim = dim3(256, 1, 1);
    cfg.dynamicSmemBytes = 0;
    cfg.stream = 0;
    cfg.attrs = attr;
    cfg.numAttrs = 1;

    cudaError_t e = cudaLaunchKernelEx(&cfg, eb_main,
                                       X, NZ, (float*)d_out, N);
    if (e != cudaSuccess) {
        (void)cudaGetLastError();
        eb_main<<<blocks, 256>>>(X, NZ, (float*)d_out, N);
    }
}